// round 6
// baseline (speedup 1.0000x reference)
#include <cuda_runtime.h>

// HEALPix padding: data [B*12, 256, 64, 64] f32, p=2 -> out [B*12, 256, 68, 68].
//
// Center rows use ONE aligned float4 load per quad + warp shuffle to realign
// the 2-column offset (output col j <- input col j-2). Border rows and edge
// quads (jq==0 / jq==16) use a uint16 gather table (face<<12 | offset), with
// the blended _tl/_br diagonal positions fixed up inline.

#define HH 64
#define P  2
#define PH 68
#define PW 68
#define NPLANE (PH*PW)        // 4624
#define NQPP   (NPLANE/4)     // 1156
#define NC  256
#define NFACE 12
#define NTAB (NFACE*NPLANE)

__device__ unsigned short g_tab16[NTAB];

__device__ __forceinline__ int idx64(int r, int c) { return r * HH + c; }

__global__ void build_table_kernel() {
    int t = blockIdx.x * blockDim.x + threadIdx.x;
    if (t >= NTAB) return;
    int f   = t / NPLANE;
    int rem = t - f * NPLANE;
    int i   = rem / PW;
    int j   = rem - i * PW;

    int ii = i - P;
    int jj = j - P;
    int rb = i - P - HH;
    int jr = j - P - HH;

    int f1 = 0, o1 = 0;

    if (f < 4) {
        // north faces: _pn
        int n   = f;
        int Ft  = (n + 1) & 3;
        int Ftl = (n + 2) & 3;
        int Fl  = (n + 3) & 3;
        int Fbl = (n + 3) & 3;
        int Fb  = n + 4;
        int Fbr = n + 8;
        int Fr  = 4 + ((n + 1) & 3);
        int Ftr = (n + 1) & 3;
        if (i < P) {
            if (j < P)            { f1 = Ftl; o1 = idx64(P-1-i, P-1-j); }
            else if (j < P + HH)  { f1 = Ft;  o1 = idx64(jj, P-1-i); }
            else                  { f1 = Ftr; o1 = idx64(HH-P+i, jr); }
        } else if (i < P + HH) {
            if (j < P)            { f1 = Fl;  o1 = idx64(P-1-j, ii); }
            else if (j < P + HH)  { f1 = n;   o1 = idx64(ii, jj); }
            else                  { f1 = Fr;  o1 = idx64(ii, jr); }
        } else {
            if (j < P)            { f1 = Fbl; o1 = idx64(rb, HH-P+j); }
            else if (j < P + HH)  { f1 = Fb;  o1 = idx64(rb, jj); }
            else                  { f1 = Fbr; o1 = idx64(rb, jr); }
        }
    } else if (f < 8) {
        // equator faces: _pe (blend diagonals store src1; pad blends inline)
        int k   = f - 4;
        int Ft  = k;
        int Fl  = (k + 3) & 3;
        int Fbl = 4 + ((k + 3) & 3);
        int Fb  = 8 + ((k + 3) & 3);
        int Fr  = 8 + k;
        int Ftr = 4 + ((k + 1) & 3);
        if (i < P) {
            if (j < P) {
                if (i == j)       { f1 = Ft; o1 = idx64(HH-P+i, 0); }
                else if (j > i)   { f1 = Ft; o1 = idx64(HH-P+i, j-i-1); }
                else              { f1 = Fl; o1 = idx64(i-j-1, HH-P+j); }
            }
            else if (j < P + HH)  { f1 = Ft;  o1 = idx64(HH-P+i, jj); }
            else                  { f1 = Ftr; o1 = idx64(HH-P+i, jr); }
        } else if (i < P + HH) {
            if (j < P)            { f1 = Fl;  o1 = idx64(ii, HH-P+j); }
            else if (j < P + HH)  { f1 = f;   o1 = idx64(ii, jj); }
            else                  { f1 = Fr;  o1 = idx64(ii, jr); }
        } else {
            if (j < P)            { f1 = Fbl; o1 = idx64(rb, HH-P+j); }
            else if (j < P + HH)  { f1 = Fb;  o1 = idx64(rb, jj); }
            else {
                if (rb == jr)     { f1 = Fb; o1 = idx64(rb, HH-1); }
                else if (jr < rb) { f1 = Fb; o1 = idx64(rb, HH-rb+jr); }
                else              { f1 = Fr; o1 = idx64(HH-jr+rb, jr); }
            }
        }
    } else {
        // south faces: _ps
        int m   = f - 8;
        int Ft  = 4 + ((m + 1) & 3);
        int Ftl = m;
        int Fl  = 4 + m;
        int Fbl = 8 + ((m + 3) & 3);
        int Fb  = 8 + ((m + 3) & 3);
        int Fbr = 8 + ((m + 2) & 3);
        int Fr  = 8 + ((m + 1) & 3);
        int Ftr = 8 + ((m + 1) & 3);
        if (i < P) {
            if (j < P)            { f1 = Ftl; o1 = idx64(HH-P+i, HH-P+j); }
            else if (j < P + HH)  { f1 = Ft;  o1 = idx64(HH-P+i, jj); }
            else                  { f1 = Ftr; o1 = idx64(HH-P+i, jr); }
        } else if (i < P + HH) {
            if (j < P)            { f1 = Fl;  o1 = idx64(ii, HH-P+j); }
            else if (j < P + HH)  { f1 = f;   o1 = idx64(ii, jj); }
            else                  { f1 = Fr;  o1 = idx64(HH-1-jr, ii); }
        } else {
            if (j < P)            { f1 = Fbl; o1 = idx64(rb, HH-P+j); }
            else if (j < P + HH)  { f1 = Fb;  o1 = idx64(jj, HH-1-rb); }
            else                  { f1 = Fbr; o1 = idx64(HH-1-rb, HH-1-jr); }
        }
    }

    g_tab16[t] = (unsigned short)((f1 << 12) | o1);
}

__global__ __launch_bounds__(256)
void pad_kernel(const float* __restrict__ in, float* __restrict__ out, int nquads) {
    int q = blockIdx.x * blockDim.x + threadIdx.x;
    if (q >= nquads) return;   // never taken: nquads == 256 * gridDim.x exactly

    int posq = q % NQPP;
    int rest = q / NQPP;          // bf*NC + ch
    int ch   = rest & (NC - 1);
    int bf   = rest >> 8;
    int b    = bf / NFACE;
    int fo   = bf - b * NFACE;

    int i  = posq / 17;           // output row (0..67)
    int jq = posq - i * 17;       // quad-in-row (0..16)

    int sbase    = ((b * NFACE) << 20) | (ch << 12);
    int facebase = sbase + (fo << 20);

    bool centerRow = (unsigned)(i - P) < HH;
    int  r    = centerRow ? (i - P) : 0;           // clamp for safe dummy load
    int  loff = (jq >= 1) ? (jq * 4 - 4) : 0;

    // One aligned float4 load per lane (dummy but safe for border lanes),
    // then realign by pulling the next lane's first two floats.
    const float4 F = __ldg(reinterpret_cast<const float4*>(in + facebase + r * HH + loff));
    float sx = __shfl_down_sync(0xffffffffu, F.x, 1);
    float sy = __shfl_down_sync(0xffffffffu, F.y, 1);

    int lane = threadIdx.x & 31;
    float4 v;

    if (centerRow && (unsigned)(jq - 1) < 15) {
        // interior quad: cols 4jq-2 .. 4jq+1 of input row
        v.x = F.z; v.y = F.w; v.z = sx; v.w = sy;
        if (lane == 31) {   // no lane+1 in this warp
            const float* row = in + facebase + r * HH;
            v.z = __ldg(row + jq * 4);
            v.w = __ldg(row + jq * 4 + 1);
        }
    } else if (centerRow && jq == 16) {
        // cols 64,65 from own row; 66,67 from table
        v.x = F.z; v.y = F.w;
        ushort2 e = *reinterpret_cast<const ushort2*>(&g_tab16[fo * NPLANE + posq * 4 + 2]);
        v.z = __ldg(in + sbase + ((e.x >> 12) << 20) + (e.x & 4095));
        v.w = __ldg(in + sbase + ((e.y >> 12) << 20) + (e.y & 4095));
    } else if (centerRow) {  // jq == 0
        ushort2 e = *reinterpret_cast<const ushort2*>(&g_tab16[fo * NPLANE + posq * 4]);
        v.x = __ldg(in + sbase + ((e.x >> 12) << 20) + (e.x & 4095));
        v.y = __ldg(in + sbase + ((e.y >> 12) << 20) + (e.y & 4095));
        v.z = sx; v.w = sy;
        if (lane == 31) {
            const float* row = in + facebase + r * HH;
            v.z = __ldg(row + 0);
            v.w = __ldg(row + 1);
        }
    } else {
        // border rows (i in {0,1,66,67}): full table gather
        const ushort4 e = *reinterpret_cast<const ushort4*>(&g_tab16[fo * NPLANE + posq * 4]);
        v.x = __ldg(in + sbase + ((e.x >> 12) << 20) + (e.x & 4095));
        v.y = __ldg(in + sbase + ((e.y >> 12) << 20) + (e.y & 4095));
        v.z = __ldg(in + sbase + ((e.z >> 12) << 20) + (e.z & 4095));
        v.w = __ldg(in + sbase + ((e.w >> 12) << 20) + (e.w & 4095));

        // blended _tl/_br diagonal positions: equator faces only
        if ((unsigned)(fo - 4) < 4) {
            int k = fo - 4;
            if (posq == 0) {            // (0,0) -> x
                v.x = 0.5f * (__ldg(in + sbase + (k << 20)             + idx64(HH-P, 0)) +
                              __ldg(in + sbase + (((k+3)&3) << 20)     + idx64(0, HH-P)));
            } else if (posq == 17) {    // (1,1) -> y
                v.y = 0.5f * (__ldg(in + sbase + (k << 20)             + idx64(HH-1, 0)) +
                              __ldg(in + sbase + (((k+3)&3) << 20)     + idx64(0, HH-1)));
            } else if (posq == 1138) {  // (66,66) -> z
                v.z = 0.5f * (__ldg(in + sbase + ((8+((k+3)&3)) << 20) + idx64(0, HH-1)) +
                              __ldg(in + sbase + ((8+k) << 20)         + idx64(HH-1, 0)));
            } else if (posq == 1155) {  // (67,67) -> w
                v.w = 0.5f * (__ldg(in + sbase + ((8+((k+3)&3)) << 20) + idx64(1, HH-1)) +
                              __ldg(in + sbase + ((8+k) << 20)         + idx64(HH-1, 1)));
            }
        }
    }

    __stcs(reinterpret_cast<float4*>(out) + q, v);
}

extern "C" void kernel_launch(void* const* d_in, const int* in_sizes, int n_in,
                              void* d_out, int out_size) {
    const float* in = (const float*)d_in[0];
    float* out = (float*)d_out;

    build_table_kernel<<<(NTAB + 255) / 256, 256>>>();

    int nquads = out_size / 4;                 // 96*256*68*68 / 4 = 28,409,856
    pad_kernel<<<(nquads + 255) / 256, 256>>>(in, out, nquads);
}

// round 7
// speedup vs baseline: 1.1757x; 1.1757x over previous
#include <cuda_runtime.h>

// HEALPix padding: data [B*12, 256, 64, 64] f32, p=2 -> out [B*12, 256, 68, 68].
//
// One block per (batch, face, channel) plane. The block stages its own 64x64
// face in shared memory (coalesced float4 loads), then emits the 68x68 output
// plane as float4 quads: center-interior quads read realigned data from smem,
// edge quads / border rows use a uint16 gather table (face<<12 | offset) with
// the blended _tl/_br diagonal positions fixed up inline.

#define HH 64
#define P  2
#define PH 68
#define PW 68
#define NPLANE (PH*PW)        // 4624
#define NQPP   (NPLANE/4)     // 1156
#define NC  256
#define NFACE 12
#define NTAB (NFACE*NPLANE)

__device__ unsigned short g_tab16[NTAB];

__device__ __forceinline__ int idx64(int r, int c) { return r * HH + c; }

__global__ void build_table_kernel() {
    int t = blockIdx.x * blockDim.x + threadIdx.x;
    if (t >= NTAB) return;
    int f   = t / NPLANE;
    int rem = t - f * NPLANE;
    int i   = rem / PW;
    int j   = rem - i * PW;

    int ii = i - P;
    int jj = j - P;
    int rb = i - P - HH;
    int jr = j - P - HH;

    int f1 = 0, o1 = 0;

    if (f < 4) {
        // north faces: _pn
        int n   = f;
        int Ft  = (n + 1) & 3;
        int Ftl = (n + 2) & 3;
        int Fl  = (n + 3) & 3;
        int Fbl = (n + 3) & 3;
        int Fb  = n + 4;
        int Fbr = n + 8;
        int Fr  = 4 + ((n + 1) & 3);
        int Ftr = (n + 1) & 3;
        if (i < P) {
            if (j < P)            { f1 = Ftl; o1 = idx64(P-1-i, P-1-j); }
            else if (j < P + HH)  { f1 = Ft;  o1 = idx64(jj, P-1-i); }
            else                  { f1 = Ftr; o1 = idx64(HH-P+i, jr); }
        } else if (i < P + HH) {
            if (j < P)            { f1 = Fl;  o1 = idx64(P-1-j, ii); }
            else if (j < P + HH)  { f1 = n;   o1 = idx64(ii, jj); }
            else                  { f1 = Fr;  o1 = idx64(ii, jr); }
        } else {
            if (j < P)            { f1 = Fbl; o1 = idx64(rb, HH-P+j); }
            else if (j < P + HH)  { f1 = Fb;  o1 = idx64(rb, jj); }
            else                  { f1 = Fbr; o1 = idx64(rb, jr); }
        }
    } else if (f < 8) {
        // equator faces: _pe (blend diagonals store src1; pad blends inline)
        int k   = f - 4;
        int Ft  = k;
        int Fl  = (k + 3) & 3;
        int Fbl = 4 + ((k + 3) & 3);
        int Fb  = 8 + ((k + 3) & 3);
        int Fr  = 8 + k;
        int Ftr = 4 + ((k + 1) & 3);
        if (i < P) {
            if (j < P) {
                if (i == j)       { f1 = Ft; o1 = idx64(HH-P+i, 0); }
                else if (j > i)   { f1 = Ft; o1 = idx64(HH-P+i, j-i-1); }
                else              { f1 = Fl; o1 = idx64(i-j-1, HH-P+j); }
            }
            else if (j < P + HH)  { f1 = Ft;  o1 = idx64(HH-P+i, jj); }
            else                  { f1 = Ftr; o1 = idx64(HH-P+i, jr); }
        } else if (i < P + HH) {
            if (j < P)            { f1 = Fl;  o1 = idx64(ii, HH-P+j); }
            else if (j < P + HH)  { f1 = f;   o1 = idx64(ii, jj); }
            else                  { f1 = Fr;  o1 = idx64(ii, jr); }
        } else {
            if (j < P)            { f1 = Fbl; o1 = idx64(rb, HH-P+j); }
            else if (j < P + HH)  { f1 = Fb;  o1 = idx64(rb, jj); }
            else {
                if (rb == jr)     { f1 = Fb; o1 = idx64(rb, HH-1); }
                else if (jr < rb) { f1 = Fb; o1 = idx64(rb, HH-rb+jr); }
                else              { f1 = Fr; o1 = idx64(HH-jr+rb, jr); }
            }
        }
    } else {
        // south faces: _ps
        int m   = f - 8;
        int Ft  = 4 + ((m + 1) & 3);
        int Ftl = m;
        int Fl  = 4 + m;
        int Fbl = 8 + ((m + 3) & 3);
        int Fb  = 8 + ((m + 3) & 3);
        int Fbr = 8 + ((m + 2) & 3);
        int Fr  = 8 + ((m + 1) & 3);
        int Ftr = 8 + ((m + 1) & 3);
        if (i < P) {
            if (j < P)            { f1 = Ftl; o1 = idx64(HH-P+i, HH-P+j); }
            else if (j < P + HH)  { f1 = Ft;  o1 = idx64(HH-P+i, jj); }
            else                  { f1 = Ftr; o1 = idx64(HH-P+i, jr); }
        } else if (i < P + HH) {
            if (j < P)            { f1 = Fl;  o1 = idx64(ii, HH-P+j); }
            else if (j < P + HH)  { f1 = f;   o1 = idx64(ii, jj); }
            else                  { f1 = Fr;  o1 = idx64(HH-1-jr, ii); }
        } else {
            if (j < P)            { f1 = Fbl; o1 = idx64(rb, HH-P+j); }
            else if (j < P + HH)  { f1 = Fb;  o1 = idx64(jj, HH-1-rb); }
            else                  { f1 = Fbr; o1 = idx64(HH-1-rb, HH-1-jr); }
        }
    }

    g_tab16[t] = (unsigned short)((f1 << 12) | o1);
}

__global__ __launch_bounds__(256)
void pad_kernel(const float* __restrict__ in, float* __restrict__ out) {
    __shared__ float s[HH * HH];          // 16 KB: own face plane

    int rest = blockIdx.x;                // bf*NC + ch
    int ch   = rest & (NC - 1);
    int bf   = rest >> 8;
    int b    = bf / NFACE;
    int fo   = bf - b * NFACE;

    int sbase = ((b * NFACE) << 20) | (ch << 12);

    // Phase 1: stage own face, fully coalesced.
    {
        const float4* face4 = reinterpret_cast<const float4*>(in + sbase + (fo << 20));
        float4* s4 = reinterpret_cast<float4*>(s);
        #pragma unroll
        for (int t = threadIdx.x; t < (HH * HH / 4); t += 256)
            s4[t] = __ldg(face4 + t);
    }
    __syncthreads();

    float4* out4 = reinterpret_cast<float4*>(out) + (size_t)rest * NQPP;
    const unsigned short* tab = &g_tab16[fo * NPLANE];

    // Phase 2: emit 1156 output quads.
    for (int q = threadIdx.x; q < NQPP; q += 256) {
        int i  = q / 17;                  // output row 0..67
        int jq = q - i * 17;              // quad-in-row 0..16

        float4 v;
        if ((unsigned)(i - P) < HH) {
            int r = i - P;
            const float* srow = s + r * HH;
            if ((unsigned)(jq - 1) < 15u) {
                // interior: input cols 4jq-2 .. 4jq+1, two aligned 8B reads
                const float2* p2 = reinterpret_cast<const float2*>(srow + jq * 4 - 2);
                float2 a = p2[0], c = p2[1];
                v = make_float4(a.x, a.y, c.x, c.y);
            } else if (jq == 0) {
                ushort2 e = *reinterpret_cast<const ushort2*>(&tab[q * 4]);
                v.x = __ldg(in + sbase + ((e.x >> 12) << 20) + (e.x & 4095));
                v.y = __ldg(in + sbase + ((e.y >> 12) << 20) + (e.y & 4095));
                v.z = srow[0];
                v.w = srow[1];
            } else {                      // jq == 16
                v.x = srow[62];
                v.y = srow[63];
                ushort2 e = *reinterpret_cast<const ushort2*>(&tab[q * 4 + 2]);
                v.z = __ldg(in + sbase + ((e.x >> 12) << 20) + (e.x & 4095));
                v.w = __ldg(in + sbase + ((e.y >> 12) << 20) + (e.y & 4095));
            }
        } else {
            // border rows (i in {0,1,66,67}): full table gather
            ushort4 e = *reinterpret_cast<const ushort4*>(&tab[q * 4]);
            v.x = __ldg(in + sbase + ((e.x >> 12) << 20) + (e.x & 4095));
            v.y = __ldg(in + sbase + ((e.y >> 12) << 20) + (e.y & 4095));
            v.z = __ldg(in + sbase + ((e.z >> 12) << 20) + (e.z & 4095));
            v.w = __ldg(in + sbase + ((e.w >> 12) << 20) + (e.w & 4095));

            // blended _tl/_br diagonal positions: equator faces only
            if ((unsigned)(fo - 4) < 4) {
                int k = fo - 4;
                if (q == 0) {             // (0,0) -> x
                    v.x = 0.5f * (__ldg(in + sbase + (k << 20)             + idx64(HH-P, 0)) +
                                  __ldg(in + sbase + (((k+3)&3) << 20)     + idx64(0, HH-P)));
                } else if (q == 17) {     // (1,1) -> y
                    v.y = 0.5f * (__ldg(in + sbase + (k << 20)             + idx64(HH-1, 0)) +
                                  __ldg(in + sbase + (((k+3)&3) << 20)     + idx64(0, HH-1)));
                } else if (q == 1138) {   // (66,66) -> z
                    v.z = 0.5f * (__ldg(in + sbase + ((8+((k+3)&3)) << 20) + idx64(0, HH-1)) +
                                  __ldg(in + sbase + ((8+k) << 20)         + idx64(HH-1, 0)));
                } else if (q == 1155) {   // (67,67) -> w
                    v.w = 0.5f * (__ldg(in + sbase + ((8+((k+3)&3)) << 20) + idx64(1, HH-1)) +
                                  __ldg(in + sbase + ((8+k) << 20)         + idx64(HH-1, 1)));
                }
            }
        }

        __stcs(out4 + q, v);
    }
}

extern "C" void kernel_launch(void* const* d_in, const int* in_sizes, int n_in,
                              void* d_out, int out_size) {
    const float* in = (const float*)d_in[0];
    float* out = (float*)d_out;

    build_table_kernel<<<(NTAB + 255) / 256, 256>>>();

    int nplanes = out_size / NPLANE;           // 96*256 = 24576 blocks
    pad_kernel<<<nplanes, 256>>>(in, out);
}

// round 9
// speedup vs baseline: 1.1809x; 1.0044x over previous
#include <cuda_runtime.h>

// HEALPix padding: data [B*12, 256, 64, 64] f32, p=2 -> out [B*12, 256, 68, 68].
//
// One block per (batch, face, channel) plane. The block stages its own 64x64
// face in shared memory (coalesced float4 loads/stores), then emits the 68x68
// output plane as float4 quads. Interior quads read TWO ALIGNED float4s from
// smem (conflict-free LDS.128) and recombine across the 2-column shift in
// registers. Edge quads / border rows use a uint16 gather table
// (face<<12 | offset) with the blended _tl/_br diagonals fixed up inline.

#define HH 64
#define P  2
#define PH 68
#define PW 68
#define NPLANE (PH*PW)        // 4624
#define NQPP   (NPLANE/4)     // 1156
#define NC  256
#define NFACE 12
#define NTAB (NFACE*NPLANE)

__device__ unsigned short g_tab16[NTAB];

__device__ __forceinline__ int idx64(int r, int c) { return r * HH + c; }

__global__ void build_table_kernel() {
    int t = blockIdx.x * blockDim.x + threadIdx.x;
    if (t >= NTAB) return;
    int f   = t / NPLANE;
    int rem = t - f * NPLANE;
    int i   = rem / PW;
    int j   = rem - i * PW;

    int ii = i - P;
    int jj = j - P;
    int rb = i - P - HH;
    int jr = j - P - HH;

    int f1 = 0, o1 = 0;

    if (f < 4) {
        // north faces: _pn
        int n   = f;
        int Ft  = (n + 1) & 3;
        int Ftl = (n + 2) & 3;
        int Fl  = (n + 3) & 3;
        int Fbl = (n + 3) & 3;
        int Fb  = n + 4;
        int Fbr = n + 8;
        int Fr  = 4 + ((n + 1) & 3);
        int Ftr = (n + 1) & 3;
        if (i < P) {
            if (j < P)            { f1 = Ftl; o1 = idx64(P-1-i, P-1-j); }
            else if (j < P + HH)  { f1 = Ft;  o1 = idx64(jj, P-1-i); }
            else                  { f1 = Ftr; o1 = idx64(HH-P+i, jr); }
        } else if (i < P + HH) {
            if (j < P)            { f1 = Fl;  o1 = idx64(P-1-j, ii); }
            else if (j < P + HH)  { f1 = n;   o1 = idx64(ii, jj); }
            else                  { f1 = Fr;  o1 = idx64(ii, jr); }
        } else {
            if (j < P)            { f1 = Fbl; o1 = idx64(rb, HH-P+j); }
            else if (j < P + HH)  { f1 = Fb;  o1 = idx64(rb, jj); }
            else                  { f1 = Fbr; o1 = idx64(rb, jr); }
        }
    } else if (f < 8) {
        // equator faces: _pe (blend diagonals store src1; pad blends inline)
        int k   = f - 4;
        int Ft  = k;
        int Fl  = (k + 3) & 3;
        int Fbl = 4 + ((k + 3) & 3);
        int Fb  = 8 + ((k + 3) & 3);
        int Fr  = 8 + k;
        int Ftr = 4 + ((k + 1) & 3);
        if (i < P) {
            if (j < P) {
                if (i == j)       { f1 = Ft; o1 = idx64(HH-P+i, 0); }
                else if (j > i)   { f1 = Ft; o1 = idx64(HH-P+i, j-i-1); }
                else              { f1 = Fl; o1 = idx64(i-j-1, HH-P+j); }
            }
            else if (j < P + HH)  { f1 = Ft;  o1 = idx64(HH-P+i, jj); }
            else                  { f1 = Ftr; o1 = idx64(HH-P+i, jr); }
        } else if (i < P + HH) {
            if (j < P)            { f1 = Fl;  o1 = idx64(ii, HH-P+j); }
            else if (j < P + HH)  { f1 = f;   o1 = idx64(ii, jj); }
            else                  { f1 = Fr;  o1 = idx64(ii, jr); }
        } else {
            if (j < P)            { f1 = Fbl; o1 = idx64(rb, HH-P+j); }
            else if (j < P + HH)  { f1 = Fb;  o1 = idx64(rb, jj); }
            else {
                if (rb == jr)     { f1 = Fb; o1 = idx64(rb, HH-1); }
                else if (jr < rb) { f1 = Fb; o1 = idx64(rb, HH-rb+jr); }
                else              { f1 = Fr; o1 = idx64(HH-jr+rb, jr); }
            }
        }
    } else {
        // south faces: _ps
        int m   = f - 8;
        int Ft  = 4 + ((m + 1) & 3);
        int Ftl = m;
        int Fl  = 4 + m;
        int Fbl = 8 + ((m + 3) & 3);
        int Fb  = 8 + ((m + 3) & 3);
        int Fbr = 8 + ((m + 2) & 3);
        int Fr  = 8 + ((m + 1) & 3);
        int Ftr = 8 + ((m + 1) & 3);
        if (i < P) {
            if (j < P)            { f1 = Ftl; o1 = idx64(HH-P+i, HH-P+j); }
            else if (j < P + HH)  { f1 = Ft;  o1 = idx64(HH-P+i, jj); }
            else                  { f1 = Ftr; o1 = idx64(HH-P+i, jr); }
        } else if (i < P + HH) {
            if (j < P)            { f1 = Fl;  o1 = idx64(ii, HH-P+j); }
            else if (j < P + HH)  { f1 = f;   o1 = idx64(ii, jj); }
            else                  { f1 = Fr;  o1 = idx64(HH-1-jr, ii); }
        } else {
            if (j < P)            { f1 = Fbl; o1 = idx64(rb, HH-P+j); }
            else if (j < P + HH)  { f1 = Fb;  o1 = idx64(jj, HH-1-rb); }
            else                  { f1 = Fbr; o1 = idx64(HH-1-rb, HH-1-jr); }
        }
    }

    g_tab16[t] = (unsigned short)((f1 << 12) | o1);
}

__global__ __launch_bounds__(256)
void pad_kernel(const float* __restrict__ in, float* __restrict__ out) {
    __shared__ float4 s4[HH * HH / 4];    // 16 KB: own face plane, 16 float4/row

    int rest = blockIdx.x;                // bf*NC + ch
    int ch   = rest & (NC - 1);
    int bf   = rest >> 8;
    int b    = bf / NFACE;
    int fo   = bf - b * NFACE;

    int sbase = ((b * NFACE) << 20) | (ch << 12);

    // Phase 1: stage own face, fully coalesced, conflict-free.
    {
        const float4* face4 = reinterpret_cast<const float4*>(in + sbase + (fo << 20));
        #pragma unroll
        for (int t = threadIdx.x; t < (HH * HH / 4); t += 256)
            s4[t] = __ldg(face4 + t);
    }
    __syncthreads();

    float4* out4 = reinterpret_cast<float4*>(out) + (size_t)rest * NQPP;
    const unsigned short* tab = &g_tab16[fo * NPLANE];

    // Phase 2: emit 1156 output quads.
    for (int q = threadIdx.x; q < NQPP; q += 256) {
        int i  = q / 17;                  // output row 0..67
        int jq = q - i * 17;              // quad-in-row 0..16

        float4 v;
        if ((unsigned)(i - P) < HH) {
            int r = i - P;
            const float4* srow4 = s4 + r * 16;
            if ((unsigned)(jq - 1) < 15u) {
                // interior: input cols 4jq-2..4jq+1 = {A.z, A.w, B.x, B.y}
                float4 A = srow4[jq - 1];
                float4 B = srow4[jq];
                v = make_float4(A.z, A.w, B.x, B.y);
            } else if (jq == 0) {
                float4 B = srow4[0];
                ushort2 e = *reinterpret_cast<const ushort2*>(&tab[q * 4]);
                v.x = __ldg(in + sbase + ((e.x >> 12) << 20) + (e.x & 4095));
                v.y = __ldg(in + sbase + ((e.y >> 12) << 20) + (e.y & 4095));
                v.z = B.x;
                v.w = B.y;
            } else {                      // jq == 16
                float4 A = srow4[15];
                v.x = A.z;
                v.y = A.w;
                ushort2 e = *reinterpret_cast<const ushort2*>(&tab[q * 4 + 2]);
                v.z = __ldg(in + sbase + ((e.x >> 12) << 20) + (e.x & 4095));
                v.w = __ldg(in + sbase + ((e.y >> 12) << 20) + (e.y & 4095));
            }
        } else {
            // border rows (i in {0,1,66,67}): full table gather
            ushort4 e = *reinterpret_cast<const ushort4*>(&tab[q * 4]);
            v.x = __ldg(in + sbase + ((e.x >> 12) << 20) + (e.x & 4095));
            v.y = __ldg(in + sbase + ((e.y >> 12) << 20) + (e.y & 4095));
            v.z = __ldg(in + sbase + ((e.z >> 12) << 20) + (e.z & 4095));
            v.w = __ldg(in + sbase + ((e.w >> 12) << 20) + (e.w & 4095));

            // blended _tl/_br diagonal positions: equator faces only
            if ((unsigned)(fo - 4) < 4) {
                int k = fo - 4;
                if (q == 0) {             // (0,0) -> x
                    v.x = 0.5f * (__ldg(in + sbase + (k << 20)             + idx64(HH-P, 0)) +
                                  __ldg(in + sbase + (((k+3)&3) << 20)     + idx64(0, HH-P)));
                } else if (q == 17) {     // (1,1) -> y
                    v.y = 0.5f * (__ldg(in + sbase + (k << 20)             + idx64(HH-1, 0)) +
                                  __ldg(in + sbase + (((k+3)&3) << 20)     + idx64(0, HH-1)));
                } else if (q == 1138) {   // (66,66) -> z
                    v.z = 0.5f * (__ldg(in + sbase + ((8+((k+3)&3)) << 20) + idx64(0, HH-1)) +
                                  __ldg(in + sbase + ((8+k) << 20)         + idx64(HH-1, 0)));
                } else if (q == 1155) {   // (67,67) -> w
                    v.w = 0.5f * (__ldg(in + sbase + ((8+((k+3)&3)) << 20) + idx64(1, HH-1)) +
                                  __ldg(in + sbase + ((8+k) << 20)         + idx64(HH-1, 1)));
                }
            }
        }

        __stcs(out4 + q, v);
    }
}

extern "C" void kernel_launch(void* const* d_in, const int* in_sizes, int n_in,
                              void* d_out, int out_size) {
    const float* in = (const float*)d_in[0];
    float* out = (float*)d_out;

    build_table_kernel<<<(NTAB + 255) / 256, 256>>>();

    int nplanes = out_size / NPLANE;           // 96*256 = 24576 blocks
    pad_kernel<<<nplanes, 256>>>(in, out);
}